// round 2
// baseline (speedup 1.0000x reference)
#include <cuda_runtime.h>

typedef unsigned long long u64;

// ---- problem constants ----
// x: [4,256,256,256] f32; w_qkv: [256,768]; b_qkv: [768]; w_proj: [256,256];
// b_proj: [256]; bias_table: [225,8]; out: [4,256,256,256] f32
// windows: 4 * 32 * 32 = 4096, 64 tokens each, 8 heads x 32 dim

#define XSTR 260   // x tile row stride (pad vs bank conflicts)
#define OSTR 260   // out tile row stride
#define QSTR 33    // q [64][32] padded
#define VSTR 34    // v [64][32] padded (even for 8B loads)
#define KSTR 68    // kT [32][64] padded (mult of 4 for float4)
#define ASTR 68    // attn [64][64] padded (mult of 4 for float4)

#define O_XS  0
#define O_OUT 16640
#define O_QS  33280
#define O_VS  35392
#define O_KT  37568
#define O_AT  39744
#define SMEM_FLOATS 44096
#define SMEM_BYTES (SMEM_FLOATS * 4)   // 176384 B

static __device__ __forceinline__ u64 pk(float lo, float hi) {
    u64 r; asm("mov.b64 %0,{%1,%2};" : "=l"(r) : "f"(lo), "f"(hi)); return r;
}
static __device__ __forceinline__ u64 pk2(float v) {
    u64 r; asm("mov.b64 %0,{%1,%1};" : "=l"(r) : "f"(v)); return r;
}
static __device__ __forceinline__ void upk(u64 v, float& lo, float& hi) {
    asm("mov.b64 {%0,%1},%2;" : "=f"(lo), "=f"(hi) : "l"(v));
}
static __device__ __forceinline__ u64 f2fma(u64 a, u64 b, u64 c) {
    u64 d; asm("fma.rn.f32x2 %0,%1,%2,%3;" : "=l"(d) : "l"(a), "l"(b), "l"(c)); return d;
}
static __device__ __forceinline__ u64 f2add(u64 a, u64 b) {
    u64 d; asm("add.rn.f32x2 %0,%1,%2;" : "=l"(d) : "l"(a), "l"(b)); return d;
}
static __device__ __forceinline__ u64 ldg64(const float* p) {
    return __ldg(reinterpret_cast<const u64*>(p));
}

__global__ void __launch_bounds__(256, 1) swin_fused(
    const float* __restrict__ x,     const float* __restrict__ wqkv,
    const float* __restrict__ bqkv,  const float* __restrict__ wproj,
    const float* __restrict__ bproj, const float* __restrict__ btab,
    float* __restrict__ y)
{
    extern __shared__ float sm[];
    float* XS   = sm + O_XS;    // [64][XSTR] window input
    float* OUTS = sm + O_OUT;   // [64][OSTR] pre-proj output
    float* QS   = sm + O_QS;    // [64][QSTR]
    float* VS   = sm + O_VS;    // [64][VSTR]
    float* KT   = sm + O_KT;    // [32][KSTR] K transposed (d-major)
    float* AT   = sm + O_AT;    // [64][ASTR] attention weights

    const int t   = threadIdx.x;
    const int wid = blockIdx.x;
    const int b   = wid >> 10;
    const int wr  = (wid >> 5) & 31;
    const int wc  = wid & 31;

    // ---- Phase A: gather rolled window into smem (float4, coalesced) ----
    {
        const int sub = t >> 6;          // 0..3  (token sub-index)
        const int v4  = (t & 63) << 2;   // 0..252 (channel offset)
        #pragma unroll
        for (int it = 0; it < 16; ++it) {
            const int tok = it * 4 + sub;
            const int gh = ((wr << 3) + (tok >> 3) + 4) & 255;
            const int gw = ((wc << 3) + (tok & 7) + 4) & 255;
            const float4 val = *reinterpret_cast<const float4*>(
                x + ((((b << 8) | gh) << 8) | gw) * 256 + v4);
            *reinterpret_cast<float4*>(&XS[tok * XSTR + v4]) = val;
        }
    }
    __syncthreads();

    const int jp = t & 15;   // output column pair (j = 2*jp, 2*jp+1)
    const int ng = t >> 4;   // row group: rows ng*4 .. ng*4+3
    const float qscale = 0.17677669529663687f;  // 1/sqrt(32)

    for (int h = 0; h < 8; ++h) {
        // ---- B1: q,k,v = xs @ Wqkv[head h] (f32x2 pairs along j) ----
        {
            const float* wq = wqkv + h * 32 + 2 * jp;
            u64 aq[4] = {0,0,0,0}, ak[4] = {0,0,0,0}, av[4] = {0,0,0,0};
            #pragma unroll 4
            for (int kk = 0; kk < 256; ++kk) {
                const float* wrow = wq + kk * 768;
                const u64 wqv = ldg64(wrow);
                const u64 wkv = ldg64(wrow + 256);
                const u64 wvv = ldg64(wrow + 512);
                #pragma unroll
                for (int i = 0; i < 4; ++i) {
                    const u64 xp = pk2(XS[(ng * 4 + i) * XSTR + kk]);
                    aq[i] = f2fma(xp, wqv, aq[i]);
                    ak[i] = f2fma(xp, wkv, ak[i]);
                    av[i] = f2fma(xp, wvv, av[i]);
                }
            }
            const float bq0 = bqkv[h*32 + 2*jp],       bq1 = bqkv[h*32 + 2*jp + 1];
            const float bk0 = bqkv[256 + h*32 + 2*jp], bk1 = bqkv[256 + h*32 + 2*jp + 1];
            const float bv0 = bqkv[512 + h*32 + 2*jp], bv1 = bqkv[512 + h*32 + 2*jp + 1];
            #pragma unroll
            for (int i = 0; i < 4; ++i) {
                const int n = ng * 4 + i;
                float lo, hi;
                upk(aq[i], lo, hi);
                QS[n * QSTR + 2*jp]     = (lo + bq0) * qscale;
                QS[n * QSTR + 2*jp + 1] = (hi + bq1) * qscale;
                upk(ak[i], lo, hi);
                KT[(2*jp)     * KSTR + n] = lo + bk0;
                KT[(2*jp + 1) * KSTR + n] = hi + bk1;
                upk(av[i], lo, hi);
                VS[n * VSTR + 2*jp]     = lo + bv0;
                VS[n * VSTR + 2*jp + 1] = hi + bv1;
            }
        }
        __syncthreads();

        // ---- B2: logits = q @ kT, + rel bias, softmax over m ----
        {
            const int n  = t >> 2;            // row 0..63
            const int m0 = (t & 3) << 4;      // 16 cols per thread
            u64 am[8] = {0,0,0,0,0,0,0,0};
            #pragma unroll 4
            for (int d = 0; d < 32; ++d) {
                const u64 qp = pk2(QS[n * QSTR + d]);
                const float* kr = &KT[d * KSTR + m0];
                #pragma unroll
                for (int u = 0; u < 4; ++u) {
                    const float4 kv = *reinterpret_cast<const float4*>(kr + 4 * u);
                    am[2*u]     = f2fma(qp, pk(kv.x, kv.y), am[2*u]);
                    am[2*u + 1] = f2fma(qp, pk(kv.z, kv.w), am[2*u + 1]);
                }
            }
            float a[16];
            #pragma unroll
            for (int p = 0; p < 8; ++p) upk(am[p], a[2*p], a[2*p + 1]);
            const int y1 = n >> 3, x1 = n & 7;
            #pragma unroll
            for (int i = 0; i < 16; ++i) {
                const int m = m0 + i;
                const int ridx = (y1 - (m >> 3) + 7) * 15 + (x1 - (m & 7) + 7);
                a[i] += __ldg(btab + ridx * 8 + h);
            }
            // softmax across the 4-thread quad owning this row
            float mx = a[0];
            #pragma unroll
            for (int i = 1; i < 16; ++i) mx = fmaxf(mx, a[i]);
            mx = fmaxf(mx, __shfl_xor_sync(0xffffffffu, mx, 1));
            mx = fmaxf(mx, __shfl_xor_sync(0xffffffffu, mx, 2));
            float s = 0.f;
            #pragma unroll
            for (int i = 0; i < 16; ++i) { a[i] = __expf(a[i] - mx); s += a[i]; }
            s += __shfl_xor_sync(0xffffffffu, s, 1);
            s += __shfl_xor_sync(0xffffffffu, s, 2);
            const float inv = 1.0f / s;
            #pragma unroll
            for (int u = 0; u < 4; ++u) {
                float4 st;
                st.x = a[4*u] * inv;     st.y = a[4*u + 1] * inv;
                st.z = a[4*u + 2] * inv; st.w = a[4*u + 3] * inv;
                *reinterpret_cast<float4*>(&AT[n * ASTR + m0 + 4 * u]) = st;
            }
        }
        __syncthreads();

        // ---- B3: out_h = attn @ V ----
        {
            u64 ao[4] = {0,0,0,0};
            #pragma unroll 4
            for (int m = 0; m < 64; ++m) {
                const u64 vv = *reinterpret_cast<const u64*>(&VS[m * VSTR + 2 * jp]);
                #pragma unroll
                for (int i = 0; i < 4; ++i)
                    ao[i] = f2fma(pk2(AT[(ng * 4 + i) * ASTR + m]), vv, ao[i]);
            }
            #pragma unroll
            for (int i = 0; i < 4; ++i)
                *reinterpret_cast<u64*>(&OUTS[(ng * 4 + i) * OSTR + h * 32 + 2 * jp]) = ao[i];
        }
        __syncthreads();
    }

    // ---- Phase C: y = outs @ w_proj + b_proj, scatter with reverse roll ----
    {
        const int cl  = t & 31;   // column-pair lane: c = 2*cl + 64*cc
        const int ng8 = t >> 5;   // rows ng8*8 .. ng8*8+7
        u64 acc[8][4];
        #pragma unroll
        for (int i = 0; i < 8; ++i)
            #pragma unroll
            for (int c = 0; c < 4; ++c) acc[i][c] = 0;

        #pragma unroll 2
        for (int k = 0; k < 256; ++k) {
            const float* wrow = wproj + k * 256 + 2 * cl;
            const u64 w0 = ldg64(wrow);
            const u64 w1 = ldg64(wrow + 64);
            const u64 w2 = ldg64(wrow + 128);
            const u64 w3 = ldg64(wrow + 192);
            #pragma unroll
            for (int i = 0; i < 8; ++i) {
                const u64 xp = pk2(OUTS[(ng8 * 8 + i) * OSTR + k]);
                acc[i][0] = f2fma(xp, w0, acc[i][0]);
                acc[i][1] = f2fma(xp, w1, acc[i][1]);
                acc[i][2] = f2fma(xp, w2, acc[i][2]);
                acc[i][3] = f2fma(xp, w3, acc[i][3]);
            }
        }
        const u64 bb0 = ldg64(bproj + 2 * cl);
        const u64 bb1 = ldg64(bproj + 2 * cl + 64);
        const u64 bb2 = ldg64(bproj + 2 * cl + 128);
        const u64 bb3 = ldg64(bproj + 2 * cl + 192);
        #pragma unroll
        for (int i = 0; i < 8; ++i) {
            const int tok = ng8 * 8 + i;
            const int gh = ((wr << 3) + (tok >> 3) + 4) & 255;
            const int gw = ((wc << 3) + (tok & 7) + 4) & 255;
            float* yrow = y + ((((b << 8) | gh) << 8) | gw) * 256 + 2 * cl;
            *reinterpret_cast<u64*>(yrow)       = f2add(acc[i][0], bb0);
            *reinterpret_cast<u64*>(yrow + 64)  = f2add(acc[i][1], bb1);
            *reinterpret_cast<u64*>(yrow + 128) = f2add(acc[i][2], bb2);
            *reinterpret_cast<u64*>(yrow + 192) = f2add(acc[i][3], bb3);
        }
    }
}

extern "C" void kernel_launch(void* const* d_in, const int* in_sizes, int n_in,
                              void* d_out, int out_size) {
    (void)in_sizes; (void)n_in; (void)out_size;
    const float* x     = (const float*)d_in[0];
    const float* wqkv  = (const float*)d_in[1];
    const float* bqkv  = (const float*)d_in[2];
    const float* wproj = (const float*)d_in[3];
    const float* bproj = (const float*)d_in[4];
    const float* btab  = (const float*)d_in[5];
    float* y = (float*)d_out;

    cudaFuncSetAttribute(swin_fused, cudaFuncAttributeMaxDynamicSharedMemorySize, SMEM_BYTES);
    swin_fused<<<4096, 256, SMEM_BYTES>>>(x, wqkv, bqkv, wproj, bproj, btab, y);
}

// round 3
// speedup vs baseline: 1.5371x; 1.5371x over previous
#include <cuda_runtime.h>

typedef unsigned long long u64;

// ---- problem constants ----
// x: [4,256,256,256] f32; w_qkv: [256,768]; b_qkv: [768]; w_proj: [256,256];
// b_proj: [256]; bias_table: [225,8]; out: [4,256,256,256] f32
// windows: 4 * 32 * 32 = 4096, 64 tokens, 8 heads x 32 dim
// 512 threads/CTA: warp-group g=0 handles heads 0-3, g=1 heads 4-7.

#define XSTR 260   // x tile row stride
#define OSTR 260   // out tile row stride
#define QSTR 34    // q [64][32] padded (even -> 8B-aligned d-pairs)
#define VSTR 34    // v [64][32] padded
#define KSTR 68    // kT [32][64] padded
#define ASTR 68    // attn [64][64] padded

#define O_XS  0        // 64*260 = 16640
#define O_OUT 16640    // 64*260 = 16640
#define O_QS  33280    // 2 * 64*34 = 4352
#define O_VS  37632    // 2 * 64*34 = 4352
#define O_KT  41984    // 2 * 32*68 = 4352
#define O_AT  46336    // 2 * 64*68 = 8704
#define SMEM_FLOATS 55040
#define SMEM_BYTES (SMEM_FLOATS * 4)   // 220160 B

static __device__ __forceinline__ u64 pk(float lo, float hi) {
    u64 r; asm("mov.b64 %0,{%1,%2};" : "=l"(r) : "f"(lo), "f"(hi)); return r;
}
static __device__ __forceinline__ u64 pk2(float v) {
    u64 r; asm("mov.b64 %0,{%1,%1};" : "=l"(r) : "f"(v)); return r;
}
static __device__ __forceinline__ void upk(u64 v, float& lo, float& hi) {
    asm("mov.b64 {%0,%1},%2;" : "=f"(lo), "=f"(hi) : "l"(v));
}
static __device__ __forceinline__ u64 f2fma(u64 a, u64 b, u64 c) {
    u64 d; asm("fma.rn.f32x2 %0,%1,%2,%3;" : "=l"(d) : "l"(a), "l"(b), "l"(c)); return d;
}
static __device__ __forceinline__ u64 f2add(u64 a, u64 b) {
    u64 d; asm("add.rn.f32x2 %0,%1,%2;" : "=l"(d) : "l"(a), "l"(b)); return d;
}
static __device__ __forceinline__ u64 ldg64(const float* p) {
    return __ldg(reinterpret_cast<const u64*>(p));
}
static __device__ __forceinline__ u64 lds64(const float* p) {
    return *reinterpret_cast<const u64*>(p);
}

__global__ void __launch_bounds__(512, 1) swin_fused(
    const float* __restrict__ x,     const float* __restrict__ wqkv,
    const float* __restrict__ bqkv,  const float* __restrict__ wproj,
    const float* __restrict__ bproj, const float* __restrict__ btab,
    float* __restrict__ y)
{
    extern __shared__ float sm[];
    float* XS   = sm + O_XS;    // [64][XSTR] window input (shared by both groups)
    float* OUTS = sm + O_OUT;   // [64][OSTR] pre-proj output (disjoint cols per group)

    const int t   = threadIdx.x;
    const int g   = t >> 8;        // head group 0/1
    const int t2  = t & 255;       // thread within group
    float* QS = sm + O_QS + g * (64 * QSTR);
    float* VS = sm + O_VS + g * (64 * VSTR);
    float* KT = sm + O_KT + g * (32 * KSTR);
    float* AT = sm + O_AT + g * (64 * ASTR);

    const int wid = blockIdx.x;
    const int b   = wid >> 10;
    const int wr  = (wid >> 5) & 31;
    const int wc  = wid & 31;

    // ---- Phase A: gather rolled window into smem (float4, coalesced) ----
    {
        const int sub = t >> 6;          // 0..7
        const int v4  = (t & 63) << 2;   // channel offset
        #pragma unroll
        for (int it = 0; it < 8; ++it) {
            const int tok = it * 8 + sub;
            const int gh = ((wr << 3) + (tok >> 3) + 4) & 255;
            const int gw = ((wc << 3) + (tok & 7) + 4) & 255;
            const float4 val = *reinterpret_cast<const float4*>(
                x + ((((b << 8) | gh) << 8) | gw) * 256 + v4);
            *reinterpret_cast<float4*>(&XS[tok * XSTR + v4]) = val;
        }
    }
    __syncthreads();

    const int jp = t2 & 15;   // output column pair (j = 2*jp, 2*jp+1)
    const int ng = t2 >> 4;   // row group: rows ng*4 .. ng*4+3
    const float qscale = 0.17677669529663687f;  // 1/sqrt(32)

    for (int hh = 0; hh < 4; ++hh) {
        const int h = (g << 2) | hh;

        // ---- B1: q,k,v = xs @ Wqkv[head h] (kk-paired, f32x2) ----
        {
            const float* wq = wqkv + h * 32 + 2 * jp;
            u64 aq[4] = {0,0,0,0}, ak[4] = {0,0,0,0}, av[4] = {0,0,0,0};
            #pragma unroll 2
            for (int kk = 0; kk < 256; kk += 2) {
                const float* wr0 = wq + kk * 768;
                const u64 wq0 = ldg64(wr0);        const u64 wq1 = ldg64(wr0 + 768);
                const u64 wk0 = ldg64(wr0 + 256);  const u64 wk1 = ldg64(wr0 + 1024);
                const u64 wv0 = ldg64(wr0 + 512);  const u64 wv1 = ldg64(wr0 + 1280);
                #pragma unroll
                for (int i = 0; i < 4; ++i) {
                    float x0, x1;
                    upk(lds64(&XS[(ng * 4 + i) * XSTR + kk]), x0, x1);
                    const u64 xp0 = pk2(x0), xp1 = pk2(x1);
                    aq[i] = f2fma(xp0, wq0, aq[i]); aq[i] = f2fma(xp1, wq1, aq[i]);
                    ak[i] = f2fma(xp0, wk0, ak[i]); ak[i] = f2fma(xp1, wk1, ak[i]);
                    av[i] = f2fma(xp0, wv0, av[i]); av[i] = f2fma(xp1, wv1, av[i]);
                }
            }
            const float bq0 = bqkv[h*32 + 2*jp],       bq1 = bqkv[h*32 + 2*jp + 1];
            const float bk0 = bqkv[256 + h*32 + 2*jp], bk1 = bqkv[256 + h*32 + 2*jp + 1];
            const float bv0 = bqkv[512 + h*32 + 2*jp], bv1 = bqkv[512 + h*32 + 2*jp + 1];
            #pragma unroll
            for (int i = 0; i < 4; ++i) {
                const int n = ng * 4 + i;
                float lo, hi;
                upk(aq[i], lo, hi);
                *reinterpret_cast<u64*>(&QS[n * QSTR + 2*jp]) =
                    pk((lo + bq0) * qscale, (hi + bq1) * qscale);
                upk(ak[i], lo, hi);
                KT[(2*jp)     * KSTR + n] = lo + bk0;
                KT[(2*jp + 1) * KSTR + n] = hi + bk1;
                upk(av[i], lo, hi);
                *reinterpret_cast<u64*>(&VS[n * VSTR + 2*jp]) = pk(lo + bv0, hi + bv1);
            }
        }
        __syncthreads();

        // ---- B2: logits = q @ kT (d-paired), + rel bias, softmax over m ----
        {
            const int n  = t2 >> 2;           // row 0..63
            const int m0 = (t2 & 3) << 4;     // 16 cols per thread
            u64 am[8] = {0,0,0,0,0,0,0,0};
            #pragma unroll 4
            for (int d = 0; d < 32; d += 2) {
                float q0, q1;
                upk(lds64(&QS[n * QSTR + d]), q0, q1);
                const u64 qp0 = pk2(q0), qp1 = pk2(q1);
                const float* kr0 = &KT[d * KSTR + m0];
                const float* kr1 = kr0 + KSTR;
                #pragma unroll
                for (int u = 0; u < 4; ++u) {
                    const float4 k0 = *reinterpret_cast<const float4*>(kr0 + 4 * u);
                    const float4 k1 = *reinterpret_cast<const float4*>(kr1 + 4 * u);
                    am[2*u]     = f2fma(qp0, pk(k0.x, k0.y), am[2*u]);
                    am[2*u]     = f2fma(qp1, pk(k1.x, k1.y), am[2*u]);
                    am[2*u + 1] = f2fma(qp0, pk(k0.z, k0.w), am[2*u + 1]);
                    am[2*u + 1] = f2fma(qp1, pk(k1.z, k1.w), am[2*u + 1]);
                }
            }
            float a[16];
            #pragma unroll
            for (int p = 0; p < 8; ++p) upk(am[p], a[2*p], a[2*p + 1]);
            const int y1 = n >> 3, x1 = n & 7;
            #pragma unroll
            for (int i = 0; i < 16; ++i) {
                const int m = m0 + i;
                const int ridx = (y1 - (m >> 3) + 7) * 15 + (x1 - (m & 7) + 7);
                a[i] += __ldg(btab + ridx * 8 + h);
            }
            // softmax across the 4-thread quad owning this row
            float mx = a[0];
            #pragma unroll
            for (int i = 1; i < 16; ++i) mx = fmaxf(mx, a[i]);
            mx = fmaxf(mx, __shfl_xor_sync(0xffffffffu, mx, 1));
            mx = fmaxf(mx, __shfl_xor_sync(0xffffffffu, mx, 2));
            float s = 0.f;
            #pragma unroll
            for (int i = 0; i < 16; ++i) { a[i] = __expf(a[i] - mx); s += a[i]; }
            s += __shfl_xor_sync(0xffffffffu, s, 1);
            s += __shfl_xor_sync(0xffffffffu, s, 2);
            const float inv = 1.0f / s;
            #pragma unroll
            for (int u = 0; u < 4; ++u) {
                float4 st;
                st.x = a[4*u] * inv;     st.y = a[4*u + 1] * inv;
                st.z = a[4*u + 2] * inv; st.w = a[4*u + 3] * inv;
                *reinterpret_cast<float4*>(&AT[n * ASTR + m0 + 4 * u]) = st;
            }
        }
        __syncthreads();

        // ---- B3: out_h = attn @ V (m-paired) ----
        {
            u64 ao[4] = {0,0,0,0};
            #pragma unroll 4
            for (int m = 0; m < 64; m += 2) {
                const u64 vv0 = lds64(&VS[m * VSTR + 2 * jp]);
                const u64 vv1 = lds64(&VS[(m + 1) * VSTR + 2 * jp]);
                #pragma unroll
                for (int i = 0; i < 4; ++i) {
                    float a0, a1;
                    upk(lds64(&AT[(ng * 4 + i) * ASTR + m]), a0, a1);
                    ao[i] = f2fma(pk2(a0), vv0, ao[i]);
                    ao[i] = f2fma(pk2(a1), vv1, ao[i]);
                }
            }
            #pragma unroll
            for (int i = 0; i < 4; ++i)
                *reinterpret_cast<u64*>(&OUTS[(ng * 4 + i) * OSTR + h * 32 + 2 * jp]) = ao[i];
        }
        __syncthreads();
    }

    // ---- Phase C: y = outs @ w_proj + b_proj, scatter with reverse roll ----
    {
        const int cl = t & 31;   // column-pair lane: c = 2*cl + 64*cc
        const int rg = t >> 5;   // rows rg*4 .. rg*4+3
        u64 acc[4][4];
        #pragma unroll
        for (int i = 0; i < 4; ++i)
            #pragma unroll
            for (int c = 0; c < 4; ++c) acc[i][c] = 0;

        #pragma unroll 2
        for (int k = 0; k < 256; k += 2) {
            const float* wr0 = wproj + k * 256 + 2 * cl;
            const u64 w00 = ldg64(wr0);       const u64 w10 = ldg64(wr0 + 256);
            const u64 w01 = ldg64(wr0 + 64);  const u64 w11 = ldg64(wr0 + 320);
            const u64 w02 = ldg64(wr0 + 128); const u64 w12 = ldg64(wr0 + 384);
            const u64 w03 = ldg64(wr0 + 192); const u64 w13 = ldg64(wr0 + 448);
            #pragma unroll
            for (int i = 0; i < 4; ++i) {
                float x0, x1;
                upk(lds64(&OUTS[(rg * 4 + i) * OSTR + k]), x0, x1);
                const u64 xp0 = pk2(x0), xp1 = pk2(x1);
                acc[i][0] = f2fma(xp0, w00, acc[i][0]); acc[i][0] = f2fma(xp1, w10, acc[i][0]);
                acc[i][1] = f2fma(xp0, w01, acc[i][1]); acc[i][1] = f2fma(xp1, w11, acc[i][1]);
                acc[i][2] = f2fma(xp0, w02, acc[i][2]); acc[i][2] = f2fma(xp1, w12, acc[i][2]);
                acc[i][3] = f2fma(xp0, w03, acc[i][3]); acc[i][3] = f2fma(xp1, w13, acc[i][3]);
            }
        }
        const u64 bb0 = ldg64(bproj + 2 * cl);
        const u64 bb1 = ldg64(bproj + 2 * cl + 64);
        const u64 bb2 = ldg64(bproj + 2 * cl + 128);
        const u64 bb3 = ldg64(bproj + 2 * cl + 192);
        #pragma unroll
        for (int i = 0; i < 4; ++i) {
            const int tok = rg * 4 + i;
            const int gh = ((wr << 3) + (tok >> 3) + 4) & 255;
            const int gw = ((wc << 3) + (tok & 7) + 4) & 255;
            float* yrow = y + ((((b << 8) | gh) << 8) | gw) * 256 + 2 * cl;
            *reinterpret_cast<u64*>(yrow)       = f2add(acc[i][0], bb0);
            *reinterpret_cast<u64*>(yrow + 64)  = f2add(acc[i][1], bb1);
            *reinterpret_cast<u64*>(yrow + 128) = f2add(acc[i][2], bb2);
            *reinterpret_cast<u64*>(yrow + 192) = f2add(acc[i][3], bb3);
        }
    }
}

extern "C" void kernel_launch(void* const* d_in, const int* in_sizes, int n_in,
                              void* d_out, int out_size) {
    (void)in_sizes; (void)n_in; (void)out_size;
    const float* x     = (const float*)d_in[0];
    const float* wqkv  = (const float*)d_in[1];
    const float* bqkv  = (const float*)d_in[2];
    const float* wproj = (const float*)d_in[3];
    const float* bproj = (const float*)d_in[4];
    const float* btab  = (const float*)d_in[5];
    float* y = (float*)d_out;

    cudaFuncSetAttribute(swin_fused, cudaFuncAttributeMaxDynamicSharedMemorySize, SMEM_BYTES);
    swin_fused<<<4096, 512, SMEM_BYTES>>>(x, wqkv, bqkv, wproj, bproj, btab, y);
}

// round 4
// speedup vs baseline: 2.7980x; 1.8203x over previous
#include <cuda_runtime.h>
#include <cstdint>

typedef unsigned long long u64;

// ---- problem constants ----
// x: [4,256,256,256] f32; w_qkv: [256,768]; b_qkv: [768]; w_proj: [256,256];
// b_proj: [256]; bias_table: [225,8]; out: [4,256,256,256] f32
// 4096 windows, 64 tokens, 8 heads x 32 dim. 512 threads/CTA, 16 warps.
// QKV + proj GEMMs: tf32 mma.sync.m16n8k8. Attention: FFMA2 fp32.

#define XSTR 260
#define OSTR 260
#define QSTR 34
#define VSTR 34
#define KSTR 68
#define ASTR 68

#define O_XS  0
#define O_OUT 16640
#define O_QS  33280
#define O_VS  37632
#define O_KT  41984
#define O_AT  46336
#define SMEM_FLOATS 55040
#define SMEM_BYTES (SMEM_FLOATS * 4)   // 220160 B

// Packed tf32 weights: layout idx(nt,ks,t,n,s) = (((nt*32+ks)*4+t)*8+n)*2+s
// where k = ks*8 + 4*s + t (s in {0,1} selects b0/b1), n = col within 8-wide tile.
// One LDG.64 per lane -> (b0,b1) fragment pair, fully coalesced per warp.
__device__ float g_qpack[768 * 256];   // qkv: nt 0..95
__device__ float g_ppack[256 * 256];   // proj: nt 0..31

__global__ void pack_w(const float* __restrict__ wqkv, const float* __restrict__ wproj) {
    const int j = blockIdx.x;
    const int k = threadIdx.x;
    const int ks = k >> 3, s = (k >> 2) & 1, tq = k & 3;
    if (j < 768) {
        uint32_t b; asm("cvt.rna.tf32.f32 %0,%1;" : "=r"(b) : "f"(wqkv[k * 768 + j]));
        const int nt = j >> 3, n = j & 7;
        g_qpack[((((nt * 32 + ks) * 4 + tq) * 8 + n) << 1) + s] = __uint_as_float(b);
    } else {
        const int jj = j - 768;
        uint32_t b; asm("cvt.rna.tf32.f32 %0,%1;" : "=r"(b) : "f"(wproj[k * 256 + jj]));
        const int nt = jj >> 3, n = jj & 7;
        g_ppack[((((nt * 32 + ks) * 4 + tq) * 8 + n) << 1) + s] = __uint_as_float(b);
    }
}

static __device__ __forceinline__ u64 pk(float lo, float hi) {
    u64 r; asm("mov.b64 %0,{%1,%2};" : "=l"(r) : "f"(lo), "f"(hi)); return r;
}
static __device__ __forceinline__ u64 pk2(float v) {
    u64 r; asm("mov.b64 %0,{%1,%1};" : "=l"(r) : "f"(v)); return r;
}
static __device__ __forceinline__ void upk(u64 v, float& lo, float& hi) {
    asm("mov.b64 {%0,%1},%2;" : "=f"(lo), "=f"(hi) : "l"(v));
}
static __device__ __forceinline__ u64 f2fma(u64 a, u64 b, u64 c) {
    u64 d; asm("fma.rn.f32x2 %0,%1,%2,%3;" : "=l"(d) : "l"(a), "l"(b), "l"(c)); return d;
}
static __device__ __forceinline__ u64 lds64(const float* p) {
    return *reinterpret_cast<const u64*>(p);
}
static __device__ __forceinline__ uint32_t tf32c(float f) {
    uint32_t r; asm("cvt.rna.tf32.f32 %0,%1;" : "=r"(r) : "f"(f)); return r;
}
static __device__ __forceinline__ void mma8(float* c, const uint32_t* a, uint32_t b0, uint32_t b1) {
    asm("mma.sync.aligned.m16n8k8.row.col.f32.tf32.tf32.f32 "
        "{%0,%1,%2,%3},{%4,%5,%6,%7},{%8,%9},{%0,%1,%2,%3};"
        : "+f"(c[0]), "+f"(c[1]), "+f"(c[2]), "+f"(c[3])
        : "r"(a[0]), "r"(a[1]), "r"(a[2]), "r"(a[3]), "r"(b0), "r"(b1));
}

__global__ void __launch_bounds__(512, 1) swin_fused(
    const float* __restrict__ x,     const float* __restrict__ bqkv,
    const float* __restrict__ bproj, const float* __restrict__ btab,
    float* __restrict__ y)
{
    extern __shared__ float sm[];
    float* XS   = sm + O_XS;
    float* OUTS = sm + O_OUT;

    const int t    = threadIdx.x;
    const int g    = t >> 8;
    const int t2   = t & 255;
    const int w    = t >> 5;
    const int lane = t & 31;
    const int gq   = lane >> 2;   // mma group id
    const int tq   = lane & 3;    // mma thread-in-group

    float* QS = sm + O_QS + g * (64 * QSTR);
    float* VS = sm + O_VS + g * (64 * VSTR);
    float* KT = sm + O_KT + g * (32 * KSTR);
    float* AT = sm + O_AT + g * (64 * ASTR);
    // B1-mma writes to the group of its warp (w>>3 == g for these threads)
    float* QSw = sm + O_QS + (w >> 3) * (64 * QSTR);
    float* VSw = sm + O_VS + (w >> 3) * (64 * VSTR);
    float* KTw = sm + O_KT + (w >> 3) * (32 * KSTR);

    const int wid = blockIdx.x;
    const int b   = wid >> 10;
    const int wr  = (wid >> 5) & 31;
    const int wc  = wid & 31;

    // ---- Phase A: gather rolled window into smem ----
    {
        const int sub = t >> 6;
        const int v4  = (t & 63) << 2;
        #pragma unroll
        for (int it = 0; it < 8; ++it) {
            const int tok = it * 8 + sub;
            const int gh = ((wr << 3) + (tok >> 3) + 4) & 255;
            const int gw = ((wc << 3) + (tok & 7) + 4) & 255;
            const float4 val = *reinterpret_cast<const float4*>(
                x + ((((b << 8) | gh) << 8) | gw) * 256 + v4);
            *reinterpret_cast<float4*>(&XS[tok * XSTR + v4]) = val;
        }
    }
    __syncthreads();

    const float qscale = 0.17677669529663687f;  // 1/sqrt(32)

    for (int hp = 0; hp < 4; ++hp) {
        // ---- B1: QKV GEMM via tf32 mma. 8 warps per head (2 heads concurrent).
        // warp w8 = w&7: m-group mg = w8&1 (m-tiles 2mg,2mg+1), col offset no=(w8>>1)*8.
        {
            const int h   = 2 * hp + (w >> 3);
            const int w8  = w & 7;
            const int mg  = w8 & 1;
            const int no  = (w8 >> 1) << 3;
            const int ntb = h * 4 + (w8 >> 1);
            const int loff = tq * 16 + gq * 2;
            const float* Bq = g_qpack + ntb * 2048 + loff;
            const float* Bk = Bq + 32 * 2048;
            const float* Bv = Bq + 64 * 2048;

            float acc[6][4];
            #pragma unroll
            for (int i = 0; i < 6; ++i)
                #pragma unroll
                for (int c = 0; c < 4; ++c) acc[i][c] = 0.f;

            #pragma unroll 4
            for (int ks = 0; ks < 32; ++ks) {
                uint32_t A[2][4];
                #pragma unroll
                for (int mi = 0; mi < 2; ++mi) {
                    const float* xr = &XS[((2 * mg + mi) * 16 + gq) * XSTR + ks * 8 + tq];
                    A[mi][0] = tf32c(xr[0]);
                    A[mi][2] = tf32c(xr[4]);
                    A[mi][1] = tf32c(xr[8 * XSTR]);
                    A[mi][3] = tf32c(xr[8 * XSTR + 4]);
                }
                const u64 bqv = lds64(Bq + ks * 64);
                const u64 bkv = lds64(Bk + ks * 64);
                const u64 bvv = lds64(Bv + ks * 64);
                const uint32_t bq0 = (uint32_t)bqv, bq1 = (uint32_t)(bqv >> 32);
                const uint32_t bk0 = (uint32_t)bkv, bk1 = (uint32_t)(bkv >> 32);
                const uint32_t bv0 = (uint32_t)bvv, bv1 = (uint32_t)(bvv >> 32);
                mma8(acc[0], A[0], bq0, bq1);  mma8(acc[1], A[1], bq0, bq1);
                mma8(acc[2], A[0], bk0, bk1);  mma8(acc[3], A[1], bk0, bk1);
                mma8(acc[4], A[0], bv0, bv1);  mma8(acc[5], A[1], bv0, bv1);
            }

            const int c0c = no + 2 * tq;                 // col within 32
            const float bqb0 = bqkv[h * 32 + c0c],       bqb1 = bqkv[h * 32 + c0c + 1];
            const float bkb0 = bqkv[256 + h * 32 + c0c], bkb1 = bqkv[256 + h * 32 + c0c + 1];
            const float bvb0 = bqkv[512 + h * 32 + c0c], bvb1 = bqkv[512 + h * 32 + c0c + 1];
            #pragma unroll
            for (int mi = 0; mi < 2; ++mi) {
                const int r = (2 * mg + mi) * 16 + gq;
                // Q (scaled, biased)
                *reinterpret_cast<u64*>(&QSw[r * QSTR + c0c]) =
                    pk((acc[mi][0] + bqb0) * qscale, (acc[mi][1] + bqb1) * qscale);
                *reinterpret_cast<u64*>(&QSw[(r + 8) * QSTR + c0c]) =
                    pk((acc[mi][2] + bqb0) * qscale, (acc[mi][3] + bqb1) * qscale);
                // K transposed
                KTw[c0c * KSTR + r]           = acc[2 + mi][0] + bkb0;
                KTw[(c0c + 1) * KSTR + r]     = acc[2 + mi][1] + bkb1;
                KTw[c0c * KSTR + r + 8]       = acc[2 + mi][2] + bkb0;
                KTw[(c0c + 1) * KSTR + r + 8] = acc[2 + mi][3] + bkb1;
                // V
                *reinterpret_cast<u64*>(&VSw[r * VSTR + c0c]) =
                    pk(acc[4 + mi][0] + bvb0, acc[4 + mi][1] + bvb1);
                *reinterpret_cast<u64*>(&VSw[(r + 8) * VSTR + c0c]) =
                    pk(acc[4 + mi][2] + bvb0, acc[4 + mi][3] + bvb1);
            }
        }
        __syncthreads();

        const int h = 2 * hp + g;

        // ---- B2: logits = q @ kT (d-paired), + rel bias, softmax ----
        {
            const int n  = t2 >> 2;
            const int m0 = (t2 & 3) << 4;
            u64 am[8] = {0,0,0,0,0,0,0,0};
            #pragma unroll 4
            for (int d = 0; d < 32; d += 2) {
                float q0, q1;
                upk(lds64(&QS[n * QSTR + d]), q0, q1);
                const u64 qp0 = pk2(q0), qp1 = pk2(q1);
                const float* kr0 = &KT[d * KSTR + m0];
                const float* kr1 = kr0 + KSTR;
                #pragma unroll
                for (int u = 0; u < 4; ++u) {
                    const float4 k0 = *reinterpret_cast<const float4*>(kr0 + 4 * u);
                    const float4 k1 = *reinterpret_cast<const float4*>(kr1 + 4 * u);
                    am[2*u]     = f2fma(qp0, pk(k0.x, k0.y), am[2*u]);
                    am[2*u]     = f2fma(qp1, pk(k1.x, k1.y), am[2*u]);
                    am[2*u + 1] = f2fma(qp0, pk(k0.z, k0.w), am[2*u + 1]);
                    am[2*u + 1] = f2fma(qp1, pk(k1.z, k1.w), am[2*u + 1]);
                }
            }
            float a[16];
            #pragma unroll
            for (int p = 0; p < 8; ++p) upk(am[p], a[2*p], a[2*p + 1]);
            const int y1 = n >> 3, x1 = n & 7;
            #pragma unroll
            for (int i = 0; i < 16; ++i) {
                const int m = m0 + i;
                const int ridx = (y1 - (m >> 3) + 7) * 15 + (x1 - (m & 7) + 7);
                a[i] += __ldg(btab + ridx * 8 + h);
            }
            float mx = a[0];
            #pragma unroll
            for (int i = 1; i < 16; ++i) mx = fmaxf(mx, a[i]);
            mx = fmaxf(mx, __shfl_xor_sync(0xffffffffu, mx, 1));
            mx = fmaxf(mx, __shfl_xor_sync(0xffffffffu, mx, 2));
            float s = 0.f;
            #pragma unroll
            for (int i = 0; i < 16; ++i) { a[i] = __expf(a[i] - mx); s += a[i]; }
            s += __shfl_xor_sync(0xffffffffu, s, 1);
            s += __shfl_xor_sync(0xffffffffu, s, 2);
            const float inv = 1.0f / s;
            #pragma unroll
            for (int u = 0; u < 4; ++u) {
                float4 st;
                st.x = a[4*u] * inv;     st.y = a[4*u + 1] * inv;
                st.z = a[4*u + 2] * inv; st.w = a[4*u + 3] * inv;
                *reinterpret_cast<float4*>(&AT[n * ASTR + m0 + 4 * u]) = st;
            }
        }
        __syncthreads();

        // ---- B3: out_h = attn @ V (m-paired) ----
        {
            const int jp = t2 & 15;
            const int ng = t2 >> 4;
            u64 ao[4] = {0,0,0,0};
            #pragma unroll 4
            for (int m = 0; m < 64; m += 2) {
                const u64 vv0 = lds64(&VS[m * VSTR + 2 * jp]);
                const u64 vv1 = lds64(&VS[(m + 1) * VSTR + 2 * jp]);
                #pragma unroll
                for (int i = 0; i < 4; ++i) {
                    float a0, a1;
                    upk(lds64(&AT[(ng * 4 + i) * ASTR + m]), a0, a1);
                    ao[i] = f2fma(pk2(a0), vv0, ao[i]);
                    ao[i] = f2fma(pk2(a1), vv1, ao[i]);
                }
            }
            #pragma unroll
            for (int i = 0; i < 4; ++i)
                *reinterpret_cast<u64*>(&OUTS[(ng * 4 + i) * OSTR + h * 32 + 2 * jp]) = ao[i];
        }
        __syncthreads();
    }

    // ---- Phase C: proj via tf32 mma. Warp w: all 4 m-tiles x n-tiles {2w, 2w+1}.
    {
        const int loff = tq * 16 + gq * 2;
        const float* Bp0 = g_ppack + (2 * w) * 2048 + loff;
        const float* Bp1 = Bp0 + 2048;

        float acc[8][4];   // [mt*2 + ntl][4]
        #pragma unroll
        for (int i = 0; i < 8; ++i)
            #pragma unroll
            for (int c = 0; c < 4; ++c) acc[i][c] = 0.f;

        #pragma unroll 2
        for (int ks = 0; ks < 32; ++ks) {
            uint32_t A[4][4];
            #pragma unroll
            for (int mt = 0; mt < 4; ++mt) {
                const float* xr = &OUTS[(mt * 16 + gq) * OSTR + ks * 8 + tq];
                A[mt][0] = tf32c(xr[0]);
                A[mt][2] = tf32c(xr[4]);
                A[mt][1] = tf32c(xr[8 * OSTR]);
                A[mt][3] = tf32c(xr[8 * OSTR + 4]);
            }
            const u64 b0v = lds64(Bp0 + ks * 64);
            const u64 b1v = lds64(Bp1 + ks * 64);
            const uint32_t b00 = (uint32_t)b0v, b01 = (uint32_t)(b0v >> 32);
            const uint32_t b10 = (uint32_t)b1v, b11 = (uint32_t)(b1v >> 32);
            #pragma unroll
            for (int mt = 0; mt < 4; ++mt) {
                mma8(acc[mt * 2],     A[mt], b00, b01);
                mma8(acc[mt * 2 + 1], A[mt], b10, b11);
            }
        }

        const int col0 = (2 * w) * 8 + 2 * tq;        // ntl=0 base col
        const float pb00 = bproj[col0],     pb01 = bproj[col0 + 1];
        const float pb10 = bproj[col0 + 8], pb11 = bproj[col0 + 9];
        #pragma unroll
        for (int mt = 0; mt < 4; ++mt) {
            const int r0 = mt * 16 + gq;
            #pragma unroll
            for (int rr = 0; rr < 2; ++rr) {
                const int tok = r0 + rr * 8;
                const int gh = ((wr << 3) + (tok >> 3) + 4) & 255;
                const int gw = ((wc << 3) + (tok & 7) + 4) & 255;
                float* yrow = y + ((((b << 8) | gh) << 8) | gw) * 256;
                *reinterpret_cast<u64*>(yrow + col0) =
                    pk(acc[mt * 2][rr * 2] + pb00, acc[mt * 2][rr * 2 + 1] + pb01);
                *reinterpret_cast<u64*>(yrow + col0 + 8) =
                    pk(acc[mt * 2 + 1][rr * 2] + pb10, acc[mt * 2 + 1][rr * 2 + 1] + pb11);
            }
        }
    }
}

extern "C" void kernel_launch(void* const* d_in, const int* in_sizes, int n_in,
                              void* d_out, int out_size) {
    (void)in_sizes; (void)n_in; (void)out_size;
    const float* x     = (const float*)d_in[0];
    const float* wqkv  = (const float*)d_in[1];
    const float* bqkv  = (const float*)d_in[2];
    const float* wproj = (const float*)d_in[3];
    const float* bproj = (const float*)d_in[4];
    const float* btab  = (const float*)d_in[5];
    float* y = (float*)d_out;

    pack_w<<<1024, 256>>>(wqkv, wproj);
    cudaFuncSetAttribute(swin_fused, cudaFuncAttributeMaxDynamicSharedMemorySize, SMEM_BYTES);
    swin_fused<<<4096, 512, SMEM_BYTES>>>(x, bqkv, bproj, btab, y);
}

// round 5
// speedup vs baseline: 4.7291x; 1.6902x over previous
#include <cuda_runtime.h>
#include <cstdint>

typedef unsigned long long u64;

// ---- problem constants ----
// x: [4,256,256,256] f32; w_qkv: [256,768]; b_qkv: [768]; w_proj: [256,256];
// b_proj: [256]; bias_table: [225,8]; out: [4,256,256,256] f32
// 4096 windows, 64 tokens, 8 heads x 32 dim. 512 threads/CTA, 16 warps.
// ALL GEMMs (QKV, Q*K^T, P*V, proj) on tf32 mma.sync.m16n8k8.

#define XSTR 260
#define OSTR 260
#define QVSTR 36   // q/k/v row stride (4*gq+tq bank pattern -> conflict-free frags)
#define ASTR 68    // attn row stride

#define O_XS  0        // 64*260 = 16640
#define O_OUT 16640    // 64*260 = 16640
#define O_QS  33280    // 2 * 64*36 = 4608
#define O_KS  37888    // 4608
#define O_VS  42496    // 4608
#define O_AT  47104    // 2 * 64*68 = 8704
#define SMEM_FLOATS 55808
#define SMEM_BYTES (SMEM_FLOATS * 4)   // 223232 B

// Packed tf32 weights: idx(nt,ks,t,n,s) = (((nt*32+ks)*4+t)*8+n)*2+s
// k = ks*8 + 4*s + t, n = col within 8-wide tile. One LDG.64/lane = (b0,b1).
__device__ float g_qpack[768 * 256];   // qkv: nt 0..95
__device__ float g_ppack[256 * 256];   // proj: nt 0..31
__device__ float g_bias[8 * 64 * 64];  // rel-pos bias, expanded [h][qtok][ktok]

__global__ void pack_w(const float* __restrict__ wqkv, const float* __restrict__ wproj) {
    const int j = blockIdx.x;
    const int k = threadIdx.x;
    const int ks = k >> 3, s = (k >> 2) & 1, tq = k & 3;
    if (j < 768) {
        uint32_t b; asm("cvt.rna.tf32.f32 %0,%1;" : "=r"(b) : "f"(wqkv[k * 768 + j]));
        const int nt = j >> 3, n = j & 7;
        g_qpack[((((nt * 32 + ks) * 4 + tq) * 8 + n) << 1) + s] = __uint_as_float(b);
    } else {
        const int jj = j - 768;
        uint32_t b; asm("cvt.rna.tf32.f32 %0,%1;" : "=r"(b) : "f"(wproj[k * 256 + jj]));
        const int nt = jj >> 3, n = jj & 7;
        g_ppack[((((nt * 32 + ks) * 4 + tq) * 8 + n) << 1) + s] = __uint_as_float(b);
    }
}

__global__ void pack_bias(const float* __restrict__ btab) {
    const int n = blockIdx.x;   // q token
    const int h = blockIdx.y;
    const int m = threadIdx.x;  // k token
    const int y1 = n >> 3, x1 = n & 7, y2 = m >> 3, x2 = m & 7;
    const int ridx = (y1 - y2 + 7) * 15 + (x1 - x2 + 7);
    g_bias[(h * 64 + n) * 64 + m] = btab[ridx * 8 + h];
}

static __device__ __forceinline__ u64 pk(float lo, float hi) {
    u64 r; asm("mov.b64 %0,{%1,%2};" : "=l"(r) : "f"(lo), "f"(hi)); return r;
}
static __device__ __forceinline__ void upk(u64 v, float& lo, float& hi) {
    asm("mov.b64 {%0,%1},%2;" : "=f"(lo), "=f"(hi) : "l"(v));
}
static __device__ __forceinline__ u64 lds64(const float* p) {
    return *reinterpret_cast<const u64*>(p);
}
static __device__ __forceinline__ uint32_t tf32c(float f) {
    uint32_t r; asm("cvt.rna.tf32.f32 %0,%1;" : "=r"(r) : "f"(f)); return r;
}
static __device__ __forceinline__ void mma8(float* c, const uint32_t* a, uint32_t b0, uint32_t b1) {
    asm("mma.sync.aligned.m16n8k8.row.col.f32.tf32.tf32.f32 "
        "{%0,%1,%2,%3},{%4,%5,%6,%7},{%8,%9},{%0,%1,%2,%3};"
        : "+f"(c[0]), "+f"(c[1]), "+f"(c[2]), "+f"(c[3])
        : "r"(a[0]), "r"(a[1]), "r"(a[2]), "r"(a[3]), "r"(b0), "r"(b1));
}

__global__ void __launch_bounds__(512, 1) swin_fused(
    const float* __restrict__ x,     const float* __restrict__ bqkv,
    const float* __restrict__ bproj, float* __restrict__ y)
{
    extern __shared__ float sm[];
    float* XS   = sm + O_XS;
    float* OUTS = sm + O_OUT;

    const int t    = threadIdx.x;
    const int g    = t >> 8;
    const int t2   = t & 255;
    const int w    = t >> 5;
    const int lane = t & 31;
    const int gq   = lane >> 2;   // mma group id (octet row)
    const int tq   = lane & 3;    // mma thread-in-group

    const int wg = w >> 3;        // warp's head-group (== g for its threads)
    float* QSw = sm + O_QS + wg * (64 * QVSTR);
    float* KSw = sm + O_KS + wg * (64 * QVSTR);
    float* VSw = sm + O_VS + wg * (64 * QVSTR);
    float* ATw = sm + O_AT + wg * (64 * ASTR);
    float* ATg = sm + O_AT + g  * (64 * ASTR);

    const int wid = blockIdx.x;
    const int b   = wid >> 10;
    const int wr  = (wid >> 5) & 31;
    const int wc  = wid & 31;

    // ---- Phase A: gather rolled window into smem ----
    {
        const int sub = t >> 6;
        const int v4  = (t & 63) << 2;
        #pragma unroll
        for (int it = 0; it < 8; ++it) {
            const int tok = it * 8 + sub;
            const int gh = ((wr << 3) + (tok >> 3) + 4) & 255;
            const int gw = ((wc << 3) + (tok & 7) + 4) & 255;
            const float4 val = *reinterpret_cast<const float4*>(
                x + ((((b << 8) | gh) << 8) | gw) * 256 + v4);
            *reinterpret_cast<float4*>(&XS[tok * XSTR + v4]) = val;
        }
    }
    __syncthreads();

    const float qscale = 0.17677669529663687f;  // 1/sqrt(32)

    for (int hp = 0; hp < 4; ++hp) {
        const int h = 2 * hp + wg;

        // ---- B1: QKV GEMM via tf32 mma (8 warps per head) ----
        {
            const int w8  = w & 7;
            const int mg  = w8 & 1;
            const int no  = (w8 >> 1) << 3;
            const int ntb = h * 4 + (w8 >> 1);
            const int loff = tq * 16 + gq * 2;
            const float* Bq = g_qpack + ntb * 2048 + loff;
            const float* Bk = Bq + 32 * 2048;
            const float* Bv = Bq + 64 * 2048;

            float acc[6][4];
            #pragma unroll
            for (int i = 0; i < 6; ++i)
                #pragma unroll
                for (int c = 0; c < 4; ++c) acc[i][c] = 0.f;

            #pragma unroll 4
            for (int ks = 0; ks < 32; ++ks) {
                uint32_t A[2][4];
                #pragma unroll
                for (int mi = 0; mi < 2; ++mi) {
                    const float* xr = &XS[((2 * mg + mi) * 16 + gq) * XSTR + ks * 8 + tq];
                    A[mi][0] = tf32c(xr[0]);
                    A[mi][2] = tf32c(xr[4]);
                    A[mi][1] = tf32c(xr[8 * XSTR]);
                    A[mi][3] = tf32c(xr[8 * XSTR + 4]);
                }
                const u64 bqv = lds64(Bq + ks * 64);
                const u64 bkv = lds64(Bk + ks * 64);
                const u64 bvv = lds64(Bv + ks * 64);
                const uint32_t bq0 = (uint32_t)bqv, bq1 = (uint32_t)(bqv >> 32);
                const uint32_t bk0 = (uint32_t)bkv, bk1 = (uint32_t)(bkv >> 32);
                const uint32_t bv0 = (uint32_t)bvv, bv1 = (uint32_t)(bvv >> 32);
                mma8(acc[0], A[0], bq0, bq1);  mma8(acc[1], A[1], bq0, bq1);
                mma8(acc[2], A[0], bk0, bk1);  mma8(acc[3], A[1], bk0, bk1);
                mma8(acc[4], A[0], bv0, bv1);  mma8(acc[5], A[1], bv0, bv1);
            }

            const int c0c = no + 2 * tq;
            const float bqb0 = bqkv[h * 32 + c0c],       bqb1 = bqkv[h * 32 + c0c + 1];
            const float bkb0 = bqkv[256 + h * 32 + c0c], bkb1 = bqkv[256 + h * 32 + c0c + 1];
            const float bvb0 = bqkv[512 + h * 32 + c0c], bvb1 = bqkv[512 + h * 32 + c0c + 1];
            #pragma unroll
            for (int mi = 0; mi < 2; ++mi) {
                const int r = (2 * mg + mi) * 16 + gq;
                *reinterpret_cast<u64*>(&QSw[r * QVSTR + c0c]) =
                    pk((acc[mi][0] + bqb0) * qscale, (acc[mi][1] + bqb1) * qscale);
                *reinterpret_cast<u64*>(&QSw[(r + 8) * QVSTR + c0c]) =
                    pk((acc[mi][2] + bqb0) * qscale, (acc[mi][3] + bqb1) * qscale);
                *reinterpret_cast<u64*>(&KSw[r * QVSTR + c0c]) =
                    pk(acc[2 + mi][0] + bkb0, acc[2 + mi][1] + bkb1);
                *reinterpret_cast<u64*>(&KSw[(r + 8) * QVSTR + c0c]) =
                    pk(acc[2 + mi][2] + bkb0, acc[2 + mi][3] + bkb1);
                *reinterpret_cast<u64*>(&VSw[r * QVSTR + c0c]) =
                    pk(acc[4 + mi][0] + bvb0, acc[4 + mi][1] + bvb1);
                *reinterpret_cast<u64*>(&VSw[(r + 8) * QVSTR + c0c]) =
                    pk(acc[4 + mi][2] + bvb0, acc[4 + mi][3] + bvb1);
            }
        }
        __syncthreads();

        // ---- S = Q @ K^T via mma: warp = (head, m-tile, n-half). Bias folded in. ----
        {
            const int w8 = w & 7;
            const int mt = w8 & 3;
            const int nh = w8 >> 2;
            const int r0 = mt * 16 + gq;

            float acc[4][4];
            #pragma unroll
            for (int i = 0; i < 4; ++i)
                #pragma unroll
                for (int c = 0; c < 4; ++c) acc[i][c] = 0.f;

            #pragma unroll
            for (int ks = 0; ks < 4; ++ks) {
                uint32_t A[4];
                const float* qr = &QSw[r0 * QVSTR + ks * 8 + tq];
                A[0] = tf32c(qr[0]);
                A[1] = tf32c(qr[8 * QVSTR]);
                A[2] = tf32c(qr[4]);
                A[3] = tf32c(qr[8 * QVSTR + 4]);
                #pragma unroll
                for (int nt = 0; nt < 4; ++nt) {
                    const float* kr = &KSw[((nh * 4 + nt) * 8 + gq) * QVSTR + ks * 8 + tq];
                    const uint32_t b0 = tf32c(kr[0]);
                    const uint32_t b1 = tf32c(kr[4]);
                    mma8(acc[nt], A, b0, b1);
                }
            }
            const float* bh = g_bias + h * 4096;
            #pragma unroll
            for (int nt = 0; nt < 4; ++nt) {
                const int c = (nh * 4 + nt) * 8 + 2 * tq;
                float b0lo, b0hi, b1lo, b1hi;
                upk(__ldg(reinterpret_cast<const u64*>(bh + r0 * 64 + c)), b0lo, b0hi);
                upk(__ldg(reinterpret_cast<const u64*>(bh + (r0 + 8) * 64 + c)), b1lo, b1hi);
                *reinterpret_cast<u64*>(&ATw[r0 * ASTR + c]) =
                    pk(acc[nt][0] + b0lo, acc[nt][1] + b0hi);
                *reinterpret_cast<u64*>(&ATw[(r0 + 8) * ASTR + c]) =
                    pk(acc[nt][2] + b1lo, acc[nt][3] + b1hi);
            }
        }
        __syncthreads();

        // ---- Softmax over AT rows (quad-per-row, in place) ----
        {
            const int n  = t2 >> 2;
            const int m0 = (t2 & 3) << 4;
            float a[16];
            #pragma unroll
            for (int u = 0; u < 4; ++u) {
                const float4 v = *reinterpret_cast<const float4*>(&ATg[n * ASTR + m0 + 4 * u]);
                a[4*u] = v.x; a[4*u+1] = v.y; a[4*u+2] = v.z; a[4*u+3] = v.w;
            }
            float mx = a[0];
            #pragma unroll
            for (int i = 1; i < 16; ++i) mx = fmaxf(mx, a[i]);
            mx = fmaxf(mx, __shfl_xor_sync(0xffffffffu, mx, 1));
            mx = fmaxf(mx, __shfl_xor_sync(0xffffffffu, mx, 2));
            float s = 0.f;
            #pragma unroll
            for (int i = 0; i < 16; ++i) { a[i] = __expf(a[i] - mx); s += a[i]; }
            s += __shfl_xor_sync(0xffffffffu, s, 1);
            s += __shfl_xor_sync(0xffffffffu, s, 2);
            const float inv = 1.0f / s;
            #pragma unroll
            for (int u = 0; u < 4; ++u) {
                float4 st;
                st.x = a[4*u] * inv;     st.y = a[4*u + 1] * inv;
                st.z = a[4*u + 2] * inv; st.w = a[4*u + 3] * inv;
                *reinterpret_cast<float4*>(&ATg[n * ASTR + m0 + 4 * u]) = st;
            }
        }
        __syncthreads();

        // ---- O = P @ V via mma: warp = (head, m-tile, n-half of 32) ----
        {
            const int w8 = w & 7;
            const int mt = w8 & 3;
            const int nh = w8 >> 2;
            const int r0 = mt * 16 + gq;

            float acc[2][4];
            #pragma unroll
            for (int i = 0; i < 2; ++i)
                #pragma unroll
                for (int c = 0; c < 4; ++c) acc[i][c] = 0.f;

            #pragma unroll
            for (int kt = 0; kt < 8; ++kt) {
                uint32_t A[4];
                const float* pr = &ATw[r0 * ASTR + kt * 8 + tq];
                A[0] = tf32c(pr[0]);
                A[1] = tf32c(pr[8 * ASTR]);
                A[2] = tf32c(pr[4]);
                A[3] = tf32c(pr[8 * ASTR + 4]);
                #pragma unroll
                for (int ntl = 0; ntl < 2; ++ntl) {
                    const float* vrp = &VSw[(kt * 8 + tq) * QVSTR + (nh * 2 + ntl) * 8 + gq];
                    const uint32_t b0 = tf32c(vrp[0]);
                    const uint32_t b1 = tf32c(vrp[4 * QVSTR]);
                    mma8(acc[ntl], A, b0, b1);
                }
            }
            #pragma unroll
            for (int ntl = 0; ntl < 2; ++ntl) {
                const int c = h * 32 + (nh * 2 + ntl) * 8 + 2 * tq;
                *reinterpret_cast<u64*>(&OUTS[r0 * OSTR + c])       = pk(acc[ntl][0], acc[ntl][1]);
                *reinterpret_cast<u64*>(&OUTS[(r0 + 8) * OSTR + c]) = pk(acc[ntl][2], acc[ntl][3]);
            }
        }
        __syncthreads();
    }

    // ---- Phase C: proj via tf32 mma. Warp w: 4 m-tiles x n-tiles {2w, 2w+1}. ----
    {
        const int loff = tq * 16 + gq * 2;
        const float* Bp0 = g_ppack + (2 * w) * 2048 + loff;
        const float* Bp1 = Bp0 + 2048;

        float acc[8][4];
        #pragma unroll
        for (int i = 0; i < 8; ++i)
            #pragma unroll
            for (int c = 0; c < 4; ++c) acc[i][c] = 0.f;

        #pragma unroll 2
        for (int ks = 0; ks < 32; ++ks) {
            uint32_t A[4][4];
            #pragma unroll
            for (int mt = 0; mt < 4; ++mt) {
                const float* xr = &OUTS[(mt * 16 + gq) * OSTR + ks * 8 + tq];
                A[mt][0] = tf32c(xr[0]);
                A[mt][2] = tf32c(xr[4]);
                A[mt][1] = tf32c(xr[8 * OSTR]);
                A[mt][3] = tf32c(xr[8 * OSTR + 4]);
            }
            const u64 b0v = lds64(Bp0 + ks * 64);
            const u64 b1v = lds64(Bp1 + ks * 64);
            const uint32_t b00 = (uint32_t)b0v, b01 = (uint32_t)(b0v >> 32);
            const uint32_t b10 = (uint32_t)b1v, b11 = (uint32_t)(b1v >> 32);
            #pragma unroll
            for (int mt = 0; mt < 4; ++mt) {
                mma8(acc[mt * 2],     A[mt], b00, b01);
                mma8(acc[mt * 2 + 1], A[mt], b10, b11);
            }
        }

        const int col0 = (2 * w) * 8 + 2 * tq;
        const float pb00 = bproj[col0],     pb01 = bproj[col0 + 1];
        const float pb10 = bproj[col0 + 8], pb11 = bproj[col0 + 9];
        #pragma unroll
        for (int mt = 0; mt < 4; ++mt) {
            const int r0 = mt * 16 + gq;
            #pragma unroll
            for (int rr = 0; rr < 2; ++rr) {
                const int tok = r0 + rr * 8;
                const int gh = ((wr << 3) + (tok >> 3) + 4) & 255;
                const int gw = ((wc << 3) + (tok & 7) + 4) & 255;
                float* yrow = y + ((((b << 8) | gh) << 8) | gw) * 256;
                *reinterpret_cast<u64*>(yrow + col0) =
                    pk(acc[mt * 2][rr * 2] + pb00, acc[mt * 2][rr * 2 + 1] + pb01);
                *reinterpret_cast<u64*>(yrow + col0 + 8) =
                    pk(acc[mt * 2 + 1][rr * 2] + pb10, acc[mt * 2 + 1][rr * 2 + 1] + pb11);
            }
        }
    }
}

extern "C" void kernel_launch(void* const* d_in, const int* in_sizes, int n_in,
                              void* d_out, int out_size) {
    (void)in_sizes; (void)n_in; (void)out_size;
    const float* x     = (const float*)d_in[0];
    const float* wqkv  = (const float*)d_in[1];
    const float* bqkv  = (const float*)d_in[2];
    const float* wproj = (const float*)d_in[3];
    const float* bproj = (const float*)d_in[4];
    const float* btab  = (const float*)d_in[5];
    float* y = (float*)d_out;

    pack_w<<<1024, 256>>>(wqkv, wproj);
    pack_bias<<<dim3(64, 8), 64>>>(btab);
    cudaFuncSetAttribute(swin_fused, cudaFuncAttributeMaxDynamicSharedMemorySize, SMEM_BYTES);
    swin_fused<<<4096, 512, SMEM_BYTES>>>(x, bqkv, bproj, y);
}

// round 6
// speedup vs baseline: 5.3554x; 1.1324x over previous
#include <cuda_runtime.h>
#include <cstdint>

typedef unsigned long long u64;

// ---- problem constants ----
// x: [4,256,256,256] f32; w_qkv: [256,768]; b_qkv: [768]; w_proj: [256,256];
// b_proj: [256]; bias_table: [225,8]; out: [4,256,256,256] f32
// 4096 windows, 64 tokens, 8 heads x 32 dim. 512 threads/CTA, 16 warps.
// All GEMMs tf32 mma.sync.m16n8k8 with PAIRED k-slots (slot0/1 = cols 2tq,2tq+1)
// so fragments load as LDS.64. All smem GEMM operands stored pre-rounded tf32.

#define XSTR 264   // (XSTR/2) % 32 == 4 -> bank8 = 4*gq+tq injective
#define OSTR 264
#define QKSTR 40   // Q/K rows: 20*gq+tq injective
#define VSTR2 36   // V rows: (2tq)*18+gq -> 8tq+gq injective
#define ASTR 72    // AT rows: 36*gq+tq -> 4*gq+tq injective

#define O_XS  0        // 64*264 = 16896
#define O_OUT 16896    // 16896
#define O_QS  33792    // 2*64*40 = 5120
#define O_KS  38912    // 5120
#define O_VS  44032    // 2*64*36 = 4608
#define O_AT  48640    // 2*64*72 = 9216
#define SMEM_FLOATS 57856
#define SMEM_BYTES (SMEM_FLOATS * 4)   // 231424 B

// Packed tf32 weights, paired-slot layout:
// within k-tile of 8: k = 2*t + s  (t=0..3 quad thread, s=0..1 slot)
// idx(nt,ks,t,n,s) = (((nt*32+ks)*4+t)*8+n)*2+s ; one LDG.64/lane = (b0,b1).
__device__ float g_qpack[768 * 256];   // qkv: nt 0..95
__device__ float g_ppack[256 * 256];   // proj: nt 0..31
__device__ float g_bias[8 * 64 * 64];  // rel-pos bias, expanded [h][qtok][ktok]

__global__ void pack_w(const float* __restrict__ wqkv, const float* __restrict__ wproj) {
    const int j = blockIdx.x;
    const int k = threadIdx.x;
    const int ks = k >> 3, kk = k & 7, tt = kk >> 1, s = kk & 1;
    if (j < 768) {
        uint32_t v; asm("cvt.rna.tf32.f32 %0,%1;" : "=r"(v) : "f"(wqkv[k * 768 + j]));
        const int nt = j >> 3, n = j & 7;
        g_qpack[((((nt * 32 + ks) * 4 + tt) * 8 + n) << 1) + s] = __uint_as_float(v);
    } else {
        const int jj = j - 768;
        uint32_t v; asm("cvt.rna.tf32.f32 %0,%1;" : "=r"(v) : "f"(wproj[k * 256 + jj]));
        const int nt = jj >> 3, n = jj & 7;
        g_ppack[((((nt * 32 + ks) * 4 + tt) * 8 + n) << 1) + s] = __uint_as_float(v);
    }
}

__global__ void pack_bias(const float* __restrict__ btab) {
    const int n = blockIdx.x;   // q token
    const int h = blockIdx.y;
    const int m = threadIdx.x;  // k token
    const int y1 = n >> 3, x1 = n & 7, y2 = m >> 3, x2 = m & 7;
    const int ridx = (y1 - y2 + 7) * 15 + (x1 - x2 + 7);
    g_bias[(h * 64 + n) * 64 + m] = btab[ridx * 8 + h];
}

static __device__ __forceinline__ u64 pk(float lo, float hi) {
    u64 r; asm("mov.b64 %0,{%1,%2};" : "=l"(r) : "f"(lo), "f"(hi)); return r;
}
static __device__ __forceinline__ void upk(u64 v, float& lo, float& hi) {
    asm("mov.b64 {%0,%1},%2;" : "=f"(lo), "=f"(hi) : "l"(v));
}
static __device__ __forceinline__ uint32_t tf32c(float f) {
    uint32_t r; asm("cvt.rna.tf32.f32 %0,%1;" : "=r"(r) : "f"(f)); return r;
}
static __device__ __forceinline__ u64 pkt(float lo, float hi) {  // tf32-rounded pair
    return pk(__uint_as_float(tf32c(lo)), __uint_as_float(tf32c(hi)));
}
static __device__ __forceinline__ void mma8(float* c, const uint32_t* a, uint32_t b0, uint32_t b1) {
    asm("mma.sync.aligned.m16n8k8.row.col.f32.tf32.tf32.f32 "
        "{%0,%1,%2,%3},{%4,%5,%6,%7},{%8,%9},{%0,%1,%2,%3};"
        : "+f"(c[0]), "+f"(c[1]), "+f"(c[2]), "+f"(c[3])
        : "r"(a[0]), "r"(a[1]), "r"(a[2]), "r"(a[3]), "r"(b0), "r"(b1));
}
static __device__ __forceinline__ void grpbar(int g) {
    asm volatile("bar.sync %0, 256;" :: "r"(g + 1) : "memory");
}

__global__ void __launch_bounds__(512, 1) swin_fused(
    const float* __restrict__ x,     const float* __restrict__ bqkv,
    const float* __restrict__ bproj, float* __restrict__ y)
{
    extern __shared__ float sm[];
    float* XS   = sm + O_XS;
    float* OUTS = sm + O_OUT;

    const int t    = threadIdx.x;
    const int g    = t >> 8;
    const int t2   = t & 255;
    const int w    = t >> 5;
    const int lane = t & 31;
    const int gq   = lane >> 2;   // octet row
    const int tq   = lane & 3;    // quad thread

    const int wg = w >> 3;        // warp's head-group (== g for its threads)
    float* QSw = sm + O_QS + wg * (64 * QKSTR);
    float* KSw = sm + O_KS + wg * (64 * QKSTR);
    float* VSw = sm + O_VS + wg * (64 * VSTR2);
    float* ATw = sm + O_AT + wg * (64 * ASTR);
    float* ATg = sm + O_AT + g  * (64 * ASTR);

    const int wid = blockIdx.x;
    const int b   = wid >> 10;
    const int wr  = (wid >> 5) & 31;
    const int wc  = wid & 31;

    // ---- Phase A: gather rolled window, round to tf32, store ----
    {
        const int sub = t >> 6;
        const int v4  = (t & 63) << 2;
        #pragma unroll
        for (int it = 0; it < 8; ++it) {
            const int tok = it * 8 + sub;
            const int gh = ((wr << 3) + (tok >> 3) + 4) & 255;
            const int gw = ((wc << 3) + (tok & 7) + 4) & 255;
            const float4 val = *reinterpret_cast<const float4*>(
                x + ((((b << 8) | gh) << 8) | gw) * 256 + v4);
            float4 rv;
            rv.x = __uint_as_float(tf32c(val.x));
            rv.y = __uint_as_float(tf32c(val.y));
            rv.z = __uint_as_float(tf32c(val.z));
            rv.w = __uint_as_float(tf32c(val.w));
            *reinterpret_cast<float4*>(&XS[tok * XSTR + v4]) = rv;
        }
    }
    __syncthreads();

    const float qscale = 0.17677669529663687f;  // 1/sqrt(32)

    for (int hp = 0; hp < 4; ++hp) {
        const int h = 2 * hp + wg;

        // ---- B1: QKV GEMM (8 warps per head) ----
        {
            const int w8  = w & 7;
            const int mg  = w8 & 1;
            const int no  = (w8 >> 1) << 3;
            const int ntb = h * 4 + (w8 >> 1);
            const int loff = tq * 16 + gq * 2;
            const float* Bq = g_qpack + ntb * 2048 + loff;
            const float* Bk = Bq + 32 * 2048;
            const float* Bv = Bq + 64 * 2048;

            float acc[6][4];
            #pragma unroll
            for (int i = 0; i < 6; ++i)
                #pragma unroll
                for (int c = 0; c < 4; ++c) acc[i][c] = 0.f;

            #pragma unroll 4
            for (int ks = 0; ks < 32; ++ks) {
                uint32_t A[2][4];
                #pragma unroll
                for (int mi = 0; mi < 2; ++mi) {
                    const int r = (2 * mg + mi) * 16 + gq;
                    const uint2 a01 = *reinterpret_cast<const uint2*>(
                        &XS[r * XSTR + ks * 8 + 2 * tq]);
                    const uint2 a23 = *reinterpret_cast<const uint2*>(
                        &XS[(r + 8) * XSTR + ks * 8 + 2 * tq]);
                    A[mi][0] = a01.x; A[mi][1] = a23.x;
                    A[mi][2] = a01.y; A[mi][3] = a23.y;
                }
                const uint2 bqv = __ldg(reinterpret_cast<const uint2*>(Bq + ks * 64));
                const uint2 bkv = __ldg(reinterpret_cast<const uint2*>(Bk + ks * 64));
                const uint2 bvv = __ldg(reinterpret_cast<const uint2*>(Bv + ks * 64));
                mma8(acc[0], A[0], bqv.x, bqv.y);  mma8(acc[1], A[1], bqv.x, bqv.y);
                mma8(acc[2], A[0], bkv.x, bkv.y);  mma8(acc[3], A[1], bkv.x, bkv.y);
                mma8(acc[4], A[0], bvv.x, bvv.y);  mma8(acc[5], A[1], bvv.x, bvv.y);
            }

            const int c0c = no + 2 * tq;
            const float bqb0 = bqkv[h * 32 + c0c],       bqb1 = bqkv[h * 32 + c0c + 1];
            const float bkb0 = bqkv[256 + h * 32 + c0c], bkb1 = bqkv[256 + h * 32 + c0c + 1];
            const float bvb0 = bqkv[512 + h * 32 + c0c], bvb1 = bqkv[512 + h * 32 + c0c + 1];
            #pragma unroll
            for (int mi = 0; mi < 2; ++mi) {
                const int r = (2 * mg + mi) * 16 + gq;
                *reinterpret_cast<u64*>(&QSw[r * QKSTR + c0c]) =
                    pkt((acc[mi][0] + bqb0) * qscale, (acc[mi][1] + bqb1) * qscale);
                *reinterpret_cast<u64*>(&QSw[(r + 8) * QKSTR + c0c]) =
                    pkt((acc[mi][2] + bqb0) * qscale, (acc[mi][3] + bqb1) * qscale);
                *reinterpret_cast<u64*>(&KSw[r * QKSTR + c0c]) =
                    pkt(acc[2 + mi][0] + bkb0, acc[2 + mi][1] + bkb1);
                *reinterpret_cast<u64*>(&KSw[(r + 8) * QKSTR + c0c]) =
                    pkt(acc[2 + mi][2] + bkb0, acc[2 + mi][3] + bkb1);
                *reinterpret_cast<u64*>(&VSw[r * VSTR2 + c0c]) =
                    pkt(acc[4 + mi][0] + bvb0, acc[4 + mi][1] + bvb1);
                *reinterpret_cast<u64*>(&VSw[(r + 8) * VSTR2 + c0c]) =
                    pkt(acc[4 + mi][2] + bvb0, acc[4 + mi][3] + bvb1);
            }
        }
        grpbar(wg);

        // ---- S = Q @ K^T : warp = (m-tile, n-half). Bias folded. ----
        {
            const int w8 = w & 7;
            const int mt = w8 & 3;
            const int nh = w8 >> 2;
            const int r0 = mt * 16 + gq;

            float acc[4][4];
            #pragma unroll
            for (int i = 0; i < 4; ++i)
                #pragma unroll
                for (int c = 0; c < 4; ++c) acc[i][c] = 0.f;

            #pragma unroll
            for (int ks = 0; ks < 4; ++ks) {
                uint32_t A[4];
                const uint2 qa = *reinterpret_cast<const uint2*>(
                    &QSw[r0 * QKSTR + ks * 8 + 2 * tq]);
                const uint2 qb = *reinterpret_cast<const uint2*>(
                    &QSw[(r0 + 8) * QKSTR + ks * 8 + 2 * tq]);
                A[0] = qa.x; A[1] = qb.x; A[2] = qa.y; A[3] = qb.y;
                #pragma unroll
                for (int nt = 0; nt < 4; ++nt) {
                    const uint2 kv = *reinterpret_cast<const uint2*>(
                        &KSw[((nh * 4 + nt) * 8 + gq) * QKSTR + ks * 8 + 2 * tq]);
                    mma8(acc[nt], A, kv.x, kv.y);
                }
            }
            const float* bh = g_bias + h * 4096;
            #pragma unroll
            for (int nt = 0; nt < 4; ++nt) {
                const int c = (nh * 4 + nt) * 8 + 2 * tq;
                float b0lo, b0hi, b1lo, b1hi;
                upk(__ldg(reinterpret_cast<const u64*>(bh + r0 * 64 + c)), b0lo, b0hi);
                upk(__ldg(reinterpret_cast<const u64*>(bh + (r0 + 8) * 64 + c)), b1lo, b1hi);
                *reinterpret_cast<u64*>(&ATw[r0 * ASTR + c]) =
                    pk(acc[nt][0] + b0lo, acc[nt][1] + b0hi);
                *reinterpret_cast<u64*>(&ATw[(r0 + 8) * ASTR + c]) =
                    pk(acc[nt][2] + b1lo, acc[nt][3] + b1hi);
            }
        }
        grpbar(wg);

        // ---- Softmax (quad-per-row, in place; store tf32-rounded probs) ----
        {
            const int n  = t2 >> 2;
            const int m0 = (t2 & 3) << 4;
            float a[16];
            #pragma unroll
            for (int u = 0; u < 4; ++u) {
                const float4 v = *reinterpret_cast<const float4*>(&ATg[n * ASTR + m0 + 4 * u]);
                a[4*u] = v.x; a[4*u+1] = v.y; a[4*u+2] = v.z; a[4*u+3] = v.w;
            }
            float mx = a[0];
            #pragma unroll
            for (int i = 1; i < 16; ++i) mx = fmaxf(mx, a[i]);
            mx = fmaxf(mx, __shfl_xor_sync(0xffffffffu, mx, 1));
            mx = fmaxf(mx, __shfl_xor_sync(0xffffffffu, mx, 2));
            float s = 0.f;
            #pragma unroll
            for (int i = 0; i < 16; ++i) { a[i] = __expf(a[i] - mx); s += a[i]; }
            s += __shfl_xor_sync(0xffffffffu, s, 1);
            s += __shfl_xor_sync(0xffffffffu, s, 2);
            const float inv = 1.0f / s;
            #pragma unroll
            for (int u = 0; u < 4; ++u) {
                float4 st;
                st.x = __uint_as_float(tf32c(a[4*u] * inv));
                st.y = __uint_as_float(tf32c(a[4*u + 1] * inv));
                st.z = __uint_as_float(tf32c(a[4*u + 2] * inv));
                st.w = __uint_as_float(tf32c(a[4*u + 3] * inv));
                *reinterpret_cast<float4*>(&ATg[n * ASTR + m0 + 4 * u]) = st;
            }
        }
        grpbar(wg);

        // ---- O = P @ V : warp = (m-tile, n-half of 32) ----
        {
            const int w8 = w & 7;
            const int mt = w8 & 3;
            const int nh = w8 >> 2;
            const int r0 = mt * 16 + gq;

            float acc[2][4];
            #pragma unroll
            for (int i = 0; i < 2; ++i)
                #pragma unroll
                for (int c = 0; c < 4; ++c) acc[i][c] = 0.f;

            #pragma unroll
            for (int kt = 0; kt < 8; ++kt) {
                uint32_t A[4];
                const uint2 p01 = *reinterpret_cast<const uint2*>(
                    &ATw[r0 * ASTR + kt * 8 + 2 * tq]);
                const uint2 p23 = *reinterpret_cast<const uint2*>(
                    &ATw[(r0 + 8) * ASTR + kt * 8 + 2 * tq]);
                A[0] = p01.x; A[1] = p23.x; A[2] = p01.y; A[3] = p23.y;
                #pragma unroll
                for (int ntl = 0; ntl < 2; ++ntl) {
                    const float* vrp = &VSw[(kt * 8 + 2 * tq) * VSTR2 + (nh * 2 + ntl) * 8 + gq];
                    const uint32_t b0 = __float_as_uint(vrp[0]);
                    const uint32_t b1 = __float_as_uint(vrp[VSTR2]);
                    mma8(acc[ntl], A, b0, b1);
                }
            }
            #pragma unroll
            for (int ntl = 0; ntl < 2; ++ntl) {
                const int c = h * 32 + (nh * 2 + ntl) * 8 + 2 * tq;
                *reinterpret_cast<u64*>(&OUTS[r0 * OSTR + c])       = pkt(acc[ntl][0], acc[ntl][1]);
                *reinterpret_cast<u64*>(&OUTS[(r0 + 8) * OSTR + c]) = pkt(acc[ntl][2], acc[ntl][3]);
            }
        }
        grpbar(wg);
    }
    __syncthreads();

    // ---- Phase C: proj. Warp w: 4 m-tiles x n-tiles {2w, 2w+1}. ----
    {
        const int loff = tq * 16 + gq * 2;
        const float* Bp0 = g_ppack + (2 * w) * 2048 + loff;
        const float* Bp1 = Bp0 + 2048;

        float acc[8][4];
        #pragma unroll
        for (int i = 0; i < 8; ++i)
            #pragma unroll
            for (int c = 0; c < 4; ++c) acc[i][c] = 0.f;

        #pragma unroll 2
        for (int ks = 0; ks < 32; ++ks) {
            uint32_t A[4][4];
            #pragma unroll
            for (int mt = 0; mt < 4; ++mt) {
                const int r = mt * 16 + gq;
                const uint2 a01 = *reinterpret_cast<const uint2*>(
                    &OUTS[r * OSTR + ks * 8 + 2 * tq]);
                const uint2 a23 = *reinterpret_cast<const uint2*>(
                    &OUTS[(r + 8) * OSTR + ks * 8 + 2 * tq]);
                A[mt][0] = a01.x; A[mt][1] = a23.x;
                A[mt][2] = a01.y; A[mt][3] = a23.y;
            }
            const uint2 b0v = __ldg(reinterpret_cast<const uint2*>(Bp0 + ks * 64));
            const uint2 b1v = __ldg(reinterpret_cast<const uint2*>(Bp1 + ks * 64));
            #pragma unroll
            for (int mt = 0; mt < 4; ++mt) {
                mma8(acc[mt * 2],     A[mt], b0v.x, b0v.y);
                mma8(acc[mt * 2 + 1], A[mt], b1v.x, b1v.y);
            }
        }

        const int col0 = (2 * w) * 8 + 2 * tq;
        const float pb00 = bproj[col0],     pb01 = bproj[col0 + 1];
        const float pb10 = bproj[col0 + 8], pb11 = bproj[col0 + 9];
        #pragma unroll
        for (int mt = 0; mt < 4; ++mt) {
            const int r0 = mt * 16 + gq;
            #pragma unroll
            for (int rr = 0; rr < 2; ++rr) {
                const int tok = r0 + rr * 8;
                const int gh = ((wr << 3) + (tok >> 3) + 4) & 255;
                const int gw = ((wc << 3) + (tok & 7) + 4) & 255;
                float* yrow = y + ((((b << 8) | gh) << 8) | gw) * 256;
                *reinterpret_cast<u64*>(yrow + col0) =
                    pk(acc[mt * 2][rr * 2] + pb00, acc[mt * 2][rr * 2 + 1] + pb01);
                *reinterpret_cast<u64*>(yrow + col0 + 8) =
                    pk(acc[mt * 2 + 1][rr * 2] + pb10, acc[mt * 2 + 1][rr * 2 + 1] + pb11);
            }
        }
    }
}

extern "C" void kernel_launch(void* const* d_in, const int* in_sizes, int n_in,
                              void* d_out, int out_size) {
    (void)in_sizes; (void)n_in; (void)out_size;
    const float* x     = (const float*)d_in[0];
    const float* wqkv  = (const float*)d_in[1];
    const float* bqkv  = (const float*)d_in[2];
    const float* wproj = (const float*)d_in[3];
    const float* bproj = (const float*)d_in[4];
    const float* btab  = (const float*)d_in[5];
    float* y = (float*)d_out;

    pack_w<<<1024, 256>>>(wqkv, wproj);
    pack_bias<<<dim3(64, 8), 64>>>(btab);
    cudaFuncSetAttribute(swin_fused, cudaFuncAttributeMaxDynamicSharedMemorySize, SMEM_BYTES);
    swin_fused<<<4096, 512, SMEM_BYTES>>>(x, bqkv, bproj, y);
}